// round 14
// baseline (speedup 1.0000x reference)
#include <cuda_runtime.h>
#include <cuda_fp16.h>
#include <cstdint>

#define TS    512
#define NBAT  512
#define HID   128
#define INP   32
#define G4    512
#define NB    8
#define HSTR  136   // padded h_sm row stride (halfs) -> conflict-free reads
#define XSTR  40    // padded x_sm row stride (halfs)
#define FSTR  136   // fc staging stride (halfs) -> conflict-free ldmatrix

// ---------------- device-global scratch (no runtime allocation allowed) ----------------
// gates i,f,o (rows [0,256) and [384,512)) pre-scaled by 0.5 in W and b:
// sigmoid(x) = tanh(acc)*0.5 + 0.5 with no runtime pre-multiply.
__device__ __half g_WencHH[G4 * HID];
__device__ __half g_WencIH[G4 * INP];
__device__ __half g_WdecHH[G4 * HID];
__device__ __half g_Wcomb [G4 * HID];
__device__ float  g_benc[G4];
__device__ float  g_bdec[G4];
__device__ __half g_fcW[INP * HID];
__device__ __half g_xT[(size_t)TS * NBAT * INP];   // [t][b][i]
__device__ __half g_dech[(size_t)TS * NBAT * HID]; // [t][b][h]

// ---------------- packed activations ----------------
__device__ __forceinline__ uint32_t u2tanh(uint32_t x) {
    uint32_t r; asm("tanh.approx.f16x2 %0, %1;" : "=r"(r) : "r"(x)); return r;
}
__device__ __forceinline__ __half2 uh2(uint32_t u) { return *reinterpret_cast<__half2*>(&u); }
__device__ __forceinline__ uint32_t h2u(__half2 h) { return *reinterpret_cast<uint32_t*>(&h); }
__device__ __forceinline__ __half2 h2tanh_(__half2 x) { return uh2(u2tanh(h2u(x))); }
// sigmoid for PRE-SCALED gates: acc already holds 0.5*x
__device__ __forceinline__ __half2 h2sig_pre(uint32_t u) {
    const __half2 h05 = __float2half2_rn(0.5f);
    return __hfma2(uh2(u2tanh(u)), h05, h05);
}

// ---------------- ldmatrix x4 ----------------
__device__ __forceinline__ void ldsm_x4(uint32_t& d0, uint32_t& d1, uint32_t& d2, uint32_t& d3,
                                        uint32_t saddr) {
    asm volatile("ldmatrix.sync.aligned.m8n8.x4.shared.b16 {%0,%1,%2,%3}, [%4];"
                 : "=r"(d0), "=r"(d1), "=r"(d2), "=r"(d3) : "r"(saddr));
}

// ---------------- mma.m16n8k16 ----------------
#define MMA16816(acc, a, b)                                                        \
    asm("mma.sync.aligned.m16n8k16.row.col.f32.f16.f16.f32 "                       \
        "{%0,%1,%2,%3}, {%4,%5,%6,%7}, {%8,%9}, {%0,%1,%2,%3};"                    \
        : "+f"(acc[0]), "+f"(acc[1]), "+f"(acc[2]), "+f"(acc[3])                   \
        : "r"(a[0]), "r"(a[1]), "r"(a[2]), "r"(a[3]), "r"(b[0]), "r"(b[1]))

#define MMA16816H(acc, a, b)                                                       \
    asm("mma.sync.aligned.m16n8k16.row.col.f16.f16.f16.f16 "                       \
        "{%0,%1}, {%2,%3,%4,%5}, {%6,%7}, {%0,%1};"                                \
        : "+r"(acc[0]), "+r"(acc[1])                                               \
        : "r"(a[0]), "r"(a[1]), "r"(a[2]), "r"(a[3]), "r"(b[0]), "r"(b[1]))

// ======================= prep: weights (0.5 gate folding) + x transpose, vectorized =======================
// One thread handles 4 consecutive elements of g_xT (same t,b; i0=4*k).
__global__ void prep_all(const float* __restrict__ x,
                         const float* __restrict__ eWih, const float* __restrict__ eWhh,
                         const float* __restrict__ ebih, const float* __restrict__ ebhh,
                         const float* __restrict__ dWih, const float* __restrict__ dWhh,
                         const float* __restrict__ dbih, const float* __restrict__ dbhh,
                         const float* __restrict__ fcW) {
    size_t n4 = (size_t)blockIdx.x * blockDim.x + threadIdx.x;   // index into xT/4

    if (n4 < ((size_t)TS * NBAT * INP) / 4) {
        size_t n = n4 * 4;
        int i = (int)(n & 31);
        int b = (int)((n >> 5) & 511);
        int t = (int)(n >> 14);
        float4 v = *(const float4*)&x[((size_t)b << 14) + (size_t)t * INP + i];
        uint2 o;
        o.x = h2u(__floats2half2_rn(v.x, v.y));
        o.y = h2u(__floats2half2_rn(v.z, v.w));
        *(uint2*)&g_xT[n] = o;
    }

    // weight conversion (low indices only; each thread handles 4 elements)
    size_t m = n4 * 4;
    if (m < G4 * HID) {
#pragma unroll
        for (int e = 0; e < 4; e++) {
            size_t k = m + e;
            int row = (int)(k >> 7);
            float s = ((row >> 7) == 2) ? 1.0f : 0.5f;   // gate g rows [256,384) unscaled
            g_WencHH[k] = __float2half(eWhh[k] * s);
            g_WdecHH[k] = __float2half(dWhh[k] * s);
            g_Wcomb[k]  = __float2half((dWih[k] + dWhh[k]) * s);
        }
    }
    if (m < G4 * INP) {
#pragma unroll
        for (int e = 0; e < 4; e++) {
            size_t k = m + e;
            int row = (int)(k >> 5);
            float s = ((row >> 7) == 2) ? 1.0f : 0.5f;
            g_WencIH[k] = __float2half(eWih[k] * s);
        }
    }
    if (m < INP * HID) {
#pragma unroll
        for (int e = 0; e < 4; e++) g_fcW[m + e] = __float2half(fcW[m + e]);
    }
    if (m < G4) {
#pragma unroll
        for (int e = 0; e < 4; e++) {
            size_t k = m + e;
            float s = (((int)k >> 7) == 2) ? 1.0f : 0.5f;
            g_benc[k] = (ebih[k] + ebhh[k]) * s;
            g_bdec[k] = (dbih[k] + dbhh[k]) * s;
        }
    }
}

// ======================= fused encoder + decoder (R12 verbatim — protected) =======================
__global__ void __launch_bounds__(256, 1) encdec_kernel() {
    __shared__ __half h_sm[2][NB * HSTR];
    __shared__ __half x_sm[2][NB * XSTR];

    const int tid  = threadIdx.x;
    const int w    = tid >> 5;
    const int lane = tid & 31;
    const int g    = lane >> 2;
    const int q    = lane & 3;
    const int bbase = blockIdx.x * NB;

    const int r0 = w * 16 + g;
    const int r1 = w * 16 + g + 8;
    const int n0 = 2 * q;
    const int n1 = 2 * q + 1;

    for (int j = tid; j < NB * HSTR; j += 256) h_sm[0][j] = __float2half(0.0f);

    // ---------------- encoder phase ----------------
    uint32_t aW[4][8][4];
    uint32_t aX[4][2][4];
#pragma unroll
    for (int G = 0; G < 4; G++) {
        const int R = G * 128 + w * 16;
#pragma unroll
        for (int kt = 0; kt < 8; kt++) {
            const int col = kt * 16 + 2 * q;
            aW[G][kt][0] = *(const uint32_t*)&g_WencHH[(R + g) * 128 + col];
            aW[G][kt][1] = *(const uint32_t*)&g_WencHH[(R + g + 8) * 128 + col];
            aW[G][kt][2] = *(const uint32_t*)&g_WencHH[(R + g) * 128 + col + 8];
            aW[G][kt][3] = *(const uint32_t*)&g_WencHH[(R + g + 8) * 128 + col + 8];
        }
#pragma unroll
        for (int kt = 0; kt < 2; kt++) {
            const int col = kt * 16 + 2 * q;
            aX[G][kt][0] = *(const uint32_t*)&g_WencIH[(R + g) * 32 + col];
            aX[G][kt][1] = *(const uint32_t*)&g_WencIH[(R + g + 8) * 32 + col];
            aX[G][kt][2] = *(const uint32_t*)&g_WencIH[(R + g) * 32 + col + 8];
            aX[G][kt][3] = *(const uint32_t*)&g_WencIH[(R + g + 8) * 32 + col + 8];
        }
    }

    uint32_t bias2[4][2];
#pragma unroll
    for (int G = 0; G < 4; G++) {
        bias2[G][0] = h2u(__half2half2(__float2half_rn(g_benc[G * 128 + r0])));
        bias2[G][1] = h2u(__half2half2(__float2half_rn(g_benc[G * 128 + r1])));
    }

    float c[4] = {0.f, 0.f, 0.f, 0.f};

    if (tid < 128) {
        uint32_t v = *(const uint32_t*)&g_xT[(size_t)bbase * INP + tid * 2];
        int b = tid >> 4, u = tid & 15;
        *(uint32_t*)&x_sm[0][b * XSTR + 2 * u] = v;
    }
    __syncthreads();

    for (int t = 0; t < TS; t++) {
        const int cur = t & 1;

        uint32_t xreg = 0;
        if (t < TS - 1 && tid < 128)
            xreg = *(const uint32_t*)&g_xT[(size_t)(t + 1) * (NBAT * INP) + (size_t)bbase * INP + tid * 2];

        uint32_t bf[8][2], bx[2][2];
#pragma unroll
        for (int kt = 0; kt < 8; kt++) {
            bf[kt][0] = *(const uint32_t*)&h_sm[cur][g * HSTR + kt * 16 + 2 * q];
            bf[kt][1] = *(const uint32_t*)&h_sm[cur][g * HSTR + kt * 16 + 2 * q + 8];
        }
#pragma unroll
        for (int kt = 0; kt < 2; kt++) {
            bx[kt][0] = *(const uint32_t*)&x_sm[cur][g * XSTR + kt * 16 + 2 * q];
            bx[kt][1] = *(const uint32_t*)&x_sm[cur][g * XSTR + kt * 16 + 2 * q + 8];
        }

        if (t < TS - 1 && tid < 128) {
            int b = tid >> 4, u = tid & 15;
            *(uint32_t*)&x_sm[cur ^ 1][b * XSTR + 2 * u] = xreg;
        }

        uint32_t acc[4][2];
#pragma unroll
        for (int G = 0; G < 4; G++) { acc[G][0] = bias2[G][0]; acc[G][1] = bias2[G][1]; }
#pragma unroll
        for (int G = 0; G < 4; G++) {
#pragma unroll
            for (int kt = 0; kt < 8; kt++) MMA16816H(acc[G], aW[G][kt], bf[kt]);
#pragma unroll
            for (int kt = 0; kt < 2; kt++) MMA16816H(acc[G], aX[G][kt], bx[kt]);
        }

        // packed gates (i,f,o pre-scaled), f32 cell state
#pragma unroll
        for (int p = 0; p < 2; p++) {
            const int j0 = 2 * p, j1 = 2 * p + 1;
            __half2 i2 = h2sig_pre(acc[0][p]);
            __half2 f2 = h2sig_pre(acc[1][p]);
            __half2 g2 = h2tanh_(uh2(acc[2][p]));
            __half2 o2 = h2sig_pre(acc[3][p]);

            float2 fi = __half22float2(i2);
            float2 ff = __half22float2(f2);
            float2 fg = __half22float2(g2);
            c[j0] = fmaf(ff.x, c[j0], fi.x * fg.x);
            c[j1] = fmaf(ff.y, c[j1], fi.y * fg.y);

            __half2 hv = __hmul2(o2, h2tanh_(__floats2half2_rn(c[j0], c[j1])));

            const int r = p ? r1 : r0;
            h_sm[cur ^ 1][n0 * HSTR + r] = __low2half(hv);
            h_sm[cur ^ 1][n1 * HSTR + r] = __high2half(hv);
        }
        __syncthreads();
    }
    // encoder done: h_T in h_sm[0]; c (fp32) in regs with exactly the decoder's layout.

    // ---------------- decoder phase ----------------
    __half2 c2p[2];
    c2p[0] = __floats2half2_rn(c[0], c[1]);
    c2p[1] = __floats2half2_rn(c[2], c[3]);

#pragma unroll
    for (int G = 0; G < 4; G++) {
        bias2[G][0] = h2u(__half2half2(__float2half_rn(g_bdec[G * 128 + r0])));
        bias2[G][1] = h2u(__half2half2(__float2half_rn(g_bdec[G * 128 + r1])));
    }

    auto load_aW = [&](const __half* Wsrc) {
#pragma unroll
        for (int G = 0; G < 4; G++) {
            const int R = G * 128 + w * 16;
#pragma unroll
            for (int kt = 0; kt < 8; kt++) {
                const int col = kt * 16 + 2 * q;
                aW[G][kt][0] = *(const uint32_t*)&Wsrc[(R + g) * 128 + col];
                aW[G][kt][1] = *(const uint32_t*)&Wsrc[(R + g + 8) * 128 + col];
                aW[G][kt][2] = *(const uint32_t*)&Wsrc[(R + g) * 128 + col + 8];
                aW[G][kt][3] = *(const uint32_t*)&Wsrc[(R + g + 8) * 128 + col + 8];
            }
        }
    };

    auto do_step = [&](int t) {
        const int cur = t & 1;
        uint32_t bf[8][2];
#pragma unroll
        for (int kt = 0; kt < 8; kt++) {
            bf[kt][0] = *(const uint32_t*)&h_sm[cur][g * HSTR + kt * 16 + 2 * q];
            bf[kt][1] = *(const uint32_t*)&h_sm[cur][g * HSTR + kt * 16 + 2 * q + 8];
        }

        uint32_t acc[4][2];
#pragma unroll
        for (int G = 0; G < 4; G++) { acc[G][0] = bias2[G][0]; acc[G][1] = bias2[G][1]; }
#pragma unroll
        for (int G = 0; G < 4; G++)
#pragma unroll
            for (int kt = 0; kt < 8; kt++) MMA16816H(acc[G], aW[G][kt], bf[kt]);

        __half* dst = &g_dech[(size_t)t * (NBAT * HID) + (size_t)bbase * HID];
#pragma unroll
        for (int p = 0; p < 2; p++) {
            __half2 i2 = h2sig_pre(acc[0][p]);
            __half2 f2 = h2sig_pre(acc[1][p]);
            __half2 g2 = h2tanh_(uh2(acc[2][p]));
            __half2 o2 = h2sig_pre(acc[3][p]);
            __half2 cn = __hfma2(f2, c2p[p], __hmul2(i2, g2));
            __half2 hv = __hmul2(o2, h2tanh_(cn));

            const int r = p ? r1 : r0;
            __half lo = __low2half(hv), hi = __high2half(hv);
            h_sm[cur ^ 1][n0 * HSTR + r] = lo;
            h_sm[cur ^ 1][n1 * HSTR + r] = hi;
            dst[n0 * HID + r] = lo;
            dst[n1 * HID + r] = hi;
        }
        __syncthreads();
    };

    load_aW(g_WdecHH);
    do_step(0);

    load_aW(g_Wcomb);
    for (int t = 1; t < TS; t++) do_step(t);
}

// ======================= FC head: 2048 CTAs, one 8-mtile chunk each =======================
__global__ void __launch_bounds__(256) fc_kernel(const float* __restrict__ fc_b,
                                                 float* __restrict__ out) {
    __shared__ __half a_sm[128 * FSTR];

    const int tid  = threadIdx.x;
    const int w    = tid >> 5;
    const int lane = tid & 31;
    const int g    = lane >> 2;
    const int q    = lane & 3;

    uint32_t bfc[4][8][2];
#pragma unroll
    for (int nt = 0; nt < 4; nt++)
#pragma unroll
        for (int kt = 0; kt < 8; kt++) {
            bfc[nt][kt][0] = *(const uint32_t*)&g_fcW[(nt * 8 + g) * HID + kt * 16 + 2 * q];
            bfc[nt][kt][1] = *(const uint32_t*)&g_fcW[(nt * 8 + g) * HID + kt * 16 + 2 * q + 8];
        }
    float fb0[4], fb1[4];
#pragma unroll
    for (int nt = 0; nt < 4; nt++) {
        fb0[nt] = fc_b[nt * 8 + 2 * q];
        fb1[nt] = fc_b[nt * 8 + 2 * q + 1];
    }

    const int arow  = (lane & 7) + ((lane & 8) ? 8 : 0);
    const int acol8 = (lane & 16) ? 8 : 0;
    const uint32_t abase = (uint32_t)__cvta_generic_to_shared(a_sm)
                         + ((w * 16 + arow) * FSTR + acol8) * 2;

    const int mt0 = blockIdx.x * 8;   // 2048 CTAs x 8 mtiles

    for (int i = tid; i < 128 * 16; i += 256) {
        int rr = i >> 4, cu = i & 15;
        uint4 v = *(const uint4*)&g_dech[((size_t)mt0 * 16 + rr) * HID + cu * 8];
        *(uint4*)&a_sm[rr * FSTR + cu * 8] = v;
    }
    __syncthreads();

    uint32_t a[8][4];
#pragma unroll
    for (int kt = 0; kt < 8; kt++)
        ldsm_x4(a[kt][0], a[kt][1], a[kt][2], a[kt][3], abase + kt * 32);

    float acc[4][4];
#pragma unroll
    for (int nt = 0; nt < 4; nt++) {
        acc[nt][0] = fb0[nt]; acc[nt][1] = fb1[nt];
        acc[nt][2] = fb0[nt]; acc[nt][3] = fb1[nt];
    }
#pragma unroll
    for (int kt = 0; kt < 8; kt++)
#pragma unroll
        for (int nt = 0; nt < 4; nt++) MMA16816(acc[nt], a[kt], bfc[nt][kt]);

    {
        const int row0 = (mt0 + w) * 16 + g;
        const int row1 = row0 + 8;
        const int b0 = row0 & 511, t0 = row0 >> 9;
        const int b1 = row1 & 511, t1 = row1 >> 9;
        float* p0 = out + (size_t)b0 * (TS * INP) + t0 * INP + 2 * q;
        float* p1 = out + (size_t)b1 * (TS * INP) + t1 * INP + 2 * q;
#pragma unroll
        for (int nt = 0; nt < 4; nt++) {
            *(float2*)(p0 + nt * 8) = make_float2(acc[nt][0], acc[nt][1]);
            *(float2*)(p1 + nt * 8) = make_float2(acc[nt][2], acc[nt][3]);
        }
    }
}

// ======================= launch =======================
extern "C" void kernel_launch(void* const* d_in, const int* in_sizes, int n_in,
                              void* d_out, int out_size) {
    const float* x     = (const float*)d_in[0];
    const float* eWih  = (const float*)d_in[1];
    const float* eWhh  = (const float*)d_in[2];
    const float* ebih  = (const float*)d_in[3];
    const float* ebhh  = (const float*)d_in[4];
    const float* dWih  = (const float*)d_in[5];
    const float* dWhh  = (const float*)d_in[6];
    const float* dbih  = (const float*)d_in[7];
    const float* dbhh  = (const float*)d_in[8];
    const float* fcW   = (const float*)d_in[9];
    const float* fcb   = (const float*)d_in[10];
    float* out = (float*)d_out;

    prep_all<<<((size_t)TS * NBAT * INP / 4 + 255) / 256, 256>>>(x, eWih, eWhh, ebih, ebhh,
                                                                 dWih, dWhh, dbih, dbhh, fcW);
    encdec_kernel<<<NBAT / NB, 256>>>();
    fc_kernel<<<2048, 256>>>(fcb, out);
}

// round 15
// speedup vs baseline: 1.0412x; 1.0412x over previous
#include <cuda_runtime.h>
#include <cuda_fp16.h>
#include <cstdint>

#define TS    512
#define NBAT  512
#define HID   128
#define INP   32
#define G4    512
#define NB    8
#define HSTR  136   // padded h_sm row stride (halfs) -> conflict-free reads
#define XSTR  40    // padded x_sm row stride (halfs)
#define FSTR  136   // fc staging stride (halfs) -> conflict-free ldmatrix

// ---------------- device-global scratch (no runtime allocation allowed) ----------------
// gates i,f,o (rows [0,256) and [384,512)) pre-scaled by 0.5 in W and b:
// sigmoid(x) = tanh(acc)*0.5 + 0.5 with no runtime pre-multiply.
__device__ __half g_WencHH[G4 * HID];
__device__ __half g_WencIH[G4 * INP];
__device__ __half g_WdecHH[G4 * HID];
__device__ __half g_Wcomb [G4 * HID];
__device__ float  g_benc[G4];
__device__ float  g_bdec[G4];
__device__ __half g_fcW[INP * HID];
__device__ __half g_xT[(size_t)TS * NBAT * INP];   // [t][b][i]
__device__ __half g_dech[(size_t)TS * NBAT * HID]; // [t][b][h]

// ---------------- packed activations ----------------
__device__ __forceinline__ uint32_t u2tanh(uint32_t x) {
    uint32_t r; asm("tanh.approx.f16x2 %0, %1;" : "=r"(r) : "r"(x)); return r;
}
__device__ __forceinline__ __half2 uh2(uint32_t u) { return *reinterpret_cast<__half2*>(&u); }
__device__ __forceinline__ uint32_t h2u(__half2 h) { return *reinterpret_cast<uint32_t*>(&h); }
__device__ __forceinline__ __half2 h2tanh_(__half2 x) { return uh2(u2tanh(h2u(x))); }
// sigmoid for PRE-SCALED gates: acc already holds 0.5*x
__device__ __forceinline__ __half2 h2sig_pre(uint32_t u) {
    const __half2 h05 = __float2half2_rn(0.5f);
    return __hfma2(uh2(u2tanh(u)), h05, h05);
}

// ---------------- ldmatrix x4 ----------------
__device__ __forceinline__ void ldsm_x4(uint32_t& d0, uint32_t& d1, uint32_t& d2, uint32_t& d3,
                                        uint32_t saddr) {
    asm volatile("ldmatrix.sync.aligned.m8n8.x4.shared.b16 {%0,%1,%2,%3}, [%4];"
                 : "=r"(d0), "=r"(d1), "=r"(d2), "=r"(d3) : "r"(saddr));
}

// ---------------- mma.m16n8k16 ----------------
#define MMA16816(acc, a, b)                                                        \
    asm("mma.sync.aligned.m16n8k16.row.col.f32.f16.f16.f32 "                       \
        "{%0,%1,%2,%3}, {%4,%5,%6,%7}, {%8,%9}, {%0,%1,%2,%3};"                    \
        : "+f"(acc[0]), "+f"(acc[1]), "+f"(acc[2]), "+f"(acc[3])                   \
        : "r"(a[0]), "r"(a[1]), "r"(a[2]), "r"(a[3]), "r"(b[0]), "r"(b[1]))

#define MMA16816H(acc, a, b)                                                       \
    asm("mma.sync.aligned.m16n8k16.row.col.f16.f16.f16.f16 "                       \
        "{%0,%1}, {%2,%3,%4,%5}, {%6,%7}, {%0,%1};"                                \
        : "+r"(acc[0]), "+r"(acc[1])                                               \
        : "r"(a[0]), "r"(a[1]), "r"(a[2]), "r"(a[3]), "r"(b[0]), "r"(b[1]))

// ======================= prep: weights (0.5 gate folding) + x transpose, vectorized x4 =======================
__global__ void prep_all(const float* __restrict__ x,
                         const float* __restrict__ eWih, const float* __restrict__ eWhh,
                         const float* __restrict__ ebih, const float* __restrict__ ebhh,
                         const float* __restrict__ dWih, const float* __restrict__ dWhh,
                         const float* __restrict__ dbih, const float* __restrict__ dbhh,
                         const float* __restrict__ fcW) {
    size_t n4 = (size_t)blockIdx.x * blockDim.x + threadIdx.x;

    if (n4 < ((size_t)TS * NBAT * INP) / 4) {
        size_t n = n4 * 4;
        int i = (int)(n & 31);
        int b = (int)((n >> 5) & 511);
        int t = (int)(n >> 14);
        float4 v = *(const float4*)&x[((size_t)b << 14) + (size_t)t * INP + i];
        uint2 o;
        o.x = h2u(__floats2half2_rn(v.x, v.y));
        o.y = h2u(__floats2half2_rn(v.z, v.w));
        *(uint2*)&g_xT[n] = o;
    }

    size_t m = n4 * 4;
    if (m < G4 * HID) {
#pragma unroll
        for (int e = 0; e < 4; e++) {
            size_t k = m + e;
            int row = (int)(k >> 7);
            float s = ((row >> 7) == 2) ? 1.0f : 0.5f;   // gate g rows [256,384) unscaled
            g_WencHH[k] = __float2half(eWhh[k] * s);
            g_WdecHH[k] = __float2half(dWhh[k] * s);
            g_Wcomb[k]  = __float2half((dWih[k] + dWhh[k]) * s);
        }
    }
    if (m < G4 * INP) {
#pragma unroll
        for (int e = 0; e < 4; e++) {
            size_t k = m + e;
            int row = (int)(k >> 5);
            float s = ((row >> 7) == 2) ? 1.0f : 0.5f;
            g_WencIH[k] = __float2half(eWih[k] * s);
        }
    }
    if (m < INP * HID) {
#pragma unroll
        for (int e = 0; e < 4; e++) g_fcW[m + e] = __float2half(fcW[m + e]);
    }
    if (m < G4) {
#pragma unroll
        for (int e = 0; e < 4; e++) {
            size_t k = m + e;
            float s = (((int)k >> 7) == 2) ? 1.0f : 0.5f;
            g_benc[k] = (ebih[k] + ebhh[k]) * s;
            g_bdec[k] = (dbih[k] + dbhh[k]) * s;
        }
    }
}

// ======================= fused encoder + decoder (R12 verbatim — protected) =======================
__global__ void __launch_bounds__(256, 1) encdec_kernel() {
    __shared__ __half h_sm[2][NB * HSTR];
    __shared__ __half x_sm[2][NB * XSTR];

    const int tid  = threadIdx.x;
    const int w    = tid >> 5;
    const int lane = tid & 31;
    const int g    = lane >> 2;
    const int q    = lane & 3;
    const int bbase = blockIdx.x * NB;

    const int r0 = w * 16 + g;
    const int r1 = w * 16 + g + 8;
    const int n0 = 2 * q;
    const int n1 = 2 * q + 1;

    for (int j = tid; j < NB * HSTR; j += 256) h_sm[0][j] = __float2half(0.0f);

    // ---------------- encoder phase ----------------
    uint32_t aW[4][8][4];
    uint32_t aX[4][2][4];
#pragma unroll
    for (int G = 0; G < 4; G++) {
        const int R = G * 128 + w * 16;
#pragma unroll
        for (int kt = 0; kt < 8; kt++) {
            const int col = kt * 16 + 2 * q;
            aW[G][kt][0] = *(const uint32_t*)&g_WencHH[(R + g) * 128 + col];
            aW[G][kt][1] = *(const uint32_t*)&g_WencHH[(R + g + 8) * 128 + col];
            aW[G][kt][2] = *(const uint32_t*)&g_WencHH[(R + g) * 128 + col + 8];
            aW[G][kt][3] = *(const uint32_t*)&g_WencHH[(R + g + 8) * 128 + col + 8];
        }
#pragma unroll
        for (int kt = 0; kt < 2; kt++) {
            const int col = kt * 16 + 2 * q;
            aX[G][kt][0] = *(const uint32_t*)&g_WencIH[(R + g) * 32 + col];
            aX[G][kt][1] = *(const uint32_t*)&g_WencIH[(R + g + 8) * 32 + col];
            aX[G][kt][2] = *(const uint32_t*)&g_WencIH[(R + g) * 32 + col + 8];
            aX[G][kt][3] = *(const uint32_t*)&g_WencIH[(R + g + 8) * 32 + col + 8];
        }
    }

    uint32_t bias2[4][2];
#pragma unroll
    for (int G = 0; G < 4; G++) {
        bias2[G][0] = h2u(__half2half2(__float2half_rn(g_benc[G * 128 + r0])));
        bias2[G][1] = h2u(__half2half2(__float2half_rn(g_benc[G * 128 + r1])));
    }

    float c[4] = {0.f, 0.f, 0.f, 0.f};

    if (tid < 128) {
        uint32_t v = *(const uint32_t*)&g_xT[(size_t)bbase * INP + tid * 2];
        int b = tid >> 4, u = tid & 15;
        *(uint32_t*)&x_sm[0][b * XSTR + 2 * u] = v;
    }
    __syncthreads();

    for (int t = 0; t < TS; t++) {
        const int cur = t & 1;

        uint32_t xreg = 0;
        if (t < TS - 1 && tid < 128)
            xreg = *(const uint32_t*)&g_xT[(size_t)(t + 1) * (NBAT * INP) + (size_t)bbase * INP + tid * 2];

        uint32_t bf[8][2], bx[2][2];
#pragma unroll
        for (int kt = 0; kt < 8; kt++) {
            bf[kt][0] = *(const uint32_t*)&h_sm[cur][g * HSTR + kt * 16 + 2 * q];
            bf[kt][1] = *(const uint32_t*)&h_sm[cur][g * HSTR + kt * 16 + 2 * q + 8];
        }
#pragma unroll
        for (int kt = 0; kt < 2; kt++) {
            bx[kt][0] = *(const uint32_t*)&x_sm[cur][g * XSTR + kt * 16 + 2 * q];
            bx[kt][1] = *(const uint32_t*)&x_sm[cur][g * XSTR + kt * 16 + 2 * q + 8];
        }

        if (t < TS - 1 && tid < 128) {
            int b = tid >> 4, u = tid & 15;
            *(uint32_t*)&x_sm[cur ^ 1][b * XSTR + 2 * u] = xreg;
        }

        uint32_t acc[4][2];
#pragma unroll
        for (int G = 0; G < 4; G++) { acc[G][0] = bias2[G][0]; acc[G][1] = bias2[G][1]; }
#pragma unroll
        for (int G = 0; G < 4; G++) {
#pragma unroll
            for (int kt = 0; kt < 8; kt++) MMA16816H(acc[G], aW[G][kt], bf[kt]);
#pragma unroll
            for (int kt = 0; kt < 2; kt++) MMA16816H(acc[G], aX[G][kt], bx[kt]);
        }

        // packed gates (i,f,o pre-scaled), f32 cell state
#pragma unroll
        for (int p = 0; p < 2; p++) {
            const int j0 = 2 * p, j1 = 2 * p + 1;
            __half2 i2 = h2sig_pre(acc[0][p]);
            __half2 f2 = h2sig_pre(acc[1][p]);
            __half2 g2 = h2tanh_(uh2(acc[2][p]));
            __half2 o2 = h2sig_pre(acc[3][p]);

            float2 fi = __half22float2(i2);
            float2 ff = __half22float2(f2);
            float2 fg = __half22float2(g2);
            c[j0] = fmaf(ff.x, c[j0], fi.x * fg.x);
            c[j1] = fmaf(ff.y, c[j1], fi.y * fg.y);

            __half2 hv = __hmul2(o2, h2tanh_(__floats2half2_rn(c[j0], c[j1])));

            const int r = p ? r1 : r0;
            h_sm[cur ^ 1][n0 * HSTR + r] = __low2half(hv);
            h_sm[cur ^ 1][n1 * HSTR + r] = __high2half(hv);
        }
        __syncthreads();
    }
    // encoder done: h_T in h_sm[0]; c (fp32) in regs with exactly the decoder's layout.

    // ---------------- decoder phase ----------------
    __half2 c2p[2];
    c2p[0] = __floats2half2_rn(c[0], c[1]);
    c2p[1] = __floats2half2_rn(c[2], c[3]);

#pragma unroll
    for (int G = 0; G < 4; G++) {
        bias2[G][0] = h2u(__half2half2(__float2half_rn(g_bdec[G * 128 + r0])));
        bias2[G][1] = h2u(__half2half2(__float2half_rn(g_bdec[G * 128 + r1])));
    }

    auto load_aW = [&](const __half* Wsrc) {
#pragma unroll
        for (int G = 0; G < 4; G++) {
            const int R = G * 128 + w * 16;
#pragma unroll
            for (int kt = 0; kt < 8; kt++) {
                const int col = kt * 16 + 2 * q;
                aW[G][kt][0] = *(const uint32_t*)&Wsrc[(R + g) * 128 + col];
                aW[G][kt][1] = *(const uint32_t*)&Wsrc[(R + g + 8) * 128 + col];
                aW[G][kt][2] = *(const uint32_t*)&Wsrc[(R + g) * 128 + col + 8];
                aW[G][kt][3] = *(const uint32_t*)&Wsrc[(R + g + 8) * 128 + col + 8];
            }
        }
    };

    auto do_step = [&](int t) {
        const int cur = t & 1;
        uint32_t bf[8][2];
#pragma unroll
        for (int kt = 0; kt < 8; kt++) {
            bf[kt][0] = *(const uint32_t*)&h_sm[cur][g * HSTR + kt * 16 + 2 * q];
            bf[kt][1] = *(const uint32_t*)&h_sm[cur][g * HSTR + kt * 16 + 2 * q + 8];
        }

        uint32_t acc[4][2];
#pragma unroll
        for (int G = 0; G < 4; G++) { acc[G][0] = bias2[G][0]; acc[G][1] = bias2[G][1]; }
#pragma unroll
        for (int G = 0; G < 4; G++)
#pragma unroll
            for (int kt = 0; kt < 8; kt++) MMA16816H(acc[G], aW[G][kt], bf[kt]);

        __half* dst = &g_dech[(size_t)t * (NBAT * HID) + (size_t)bbase * HID];
#pragma unroll
        for (int p = 0; p < 2; p++) {
            __half2 i2 = h2sig_pre(acc[0][p]);
            __half2 f2 = h2sig_pre(acc[1][p]);
            __half2 g2 = h2tanh_(uh2(acc[2][p]));
            __half2 o2 = h2sig_pre(acc[3][p]);
            __half2 cn = __hfma2(f2, c2p[p], __hmul2(i2, g2));
            __half2 hv = __hmul2(o2, h2tanh_(cn));

            const int r = p ? r1 : r0;
            __half lo = __low2half(hv), hi = __high2half(hv);
            h_sm[cur ^ 1][n0 * HSTR + r] = lo;
            h_sm[cur ^ 1][n1 * HSTR + r] = hi;
            dst[n0 * HID + r] = lo;
            dst[n1 * HID + r] = hi;
        }
        __syncthreads();
    };

    load_aW(g_WdecHH);
    do_step(0);

    load_aW(g_Wcomb);
    for (int t = 1; t < TS; t++) do_step(t);
}

// ======================= FC head: 1024 CTAs x 2 chunks (R12 proven config) =======================
__global__ void __launch_bounds__(256) fc_kernel(const float* __restrict__ fc_b,
                                                 float* __restrict__ out) {
    __shared__ __half a_sm[128 * FSTR];

    const int tid  = threadIdx.x;
    const int w    = tid >> 5;
    const int lane = tid & 31;
    const int g    = lane >> 2;
    const int q    = lane & 3;

    uint32_t bfc[4][8][2];
#pragma unroll
    for (int nt = 0; nt < 4; nt++)
#pragma unroll
        for (int kt = 0; kt < 8; kt++) {
            bfc[nt][kt][0] = *(const uint32_t*)&g_fcW[(nt * 8 + g) * HID + kt * 16 + 2 * q];
            bfc[nt][kt][1] = *(const uint32_t*)&g_fcW[(nt * 8 + g) * HID + kt * 16 + 2 * q + 8];
        }
    float fb0[4], fb1[4];
#pragma unroll
    for (int nt = 0; nt < 4; nt++) {
        fb0[nt] = fc_b[nt * 8 + 2 * q];
        fb1[nt] = fc_b[nt * 8 + 2 * q + 1];
    }

    const int arow  = (lane & 7) + ((lane & 8) ? 8 : 0);
    const int acol8 = (lane & 16) ? 8 : 0;
    const uint32_t abase = (uint32_t)__cvta_generic_to_shared(a_sm)
                         + ((w * 16 + arow) * FSTR + acol8) * 2;

    for (int chunk = 0; chunk < 2; chunk++) {
        const int mt0 = blockIdx.x * 16 + chunk * 8;

        for (int i = tid; i < 128 * 16; i += 256) {
            int rr = i >> 4, cu = i & 15;
            uint4 v = *(const uint4*)&g_dech[((size_t)mt0 * 16 + rr) * HID + cu * 8];
            *(uint4*)&a_sm[rr * FSTR + cu * 8] = v;
        }
        __syncthreads();

        uint32_t a[8][4];
#pragma unroll
        for (int kt = 0; kt < 8; kt++)
            ldsm_x4(a[kt][0], a[kt][1], a[kt][2], a[kt][3], abase + kt * 32);

        float acc[4][4];
#pragma unroll
        for (int nt = 0; nt < 4; nt++) {
            acc[nt][0] = fb0[nt]; acc[nt][1] = fb1[nt];
            acc[nt][2] = fb0[nt]; acc[nt][3] = fb1[nt];
        }
#pragma unroll
        for (int kt = 0; kt < 8; kt++)
#pragma unroll
            for (int nt = 0; nt < 4; nt++) MMA16816(acc[nt], a[kt], bfc[nt][kt]);

        {
            const int row0 = (mt0 + w) * 16 + g;
            const int row1 = row0 + 8;
            const int b0 = row0 & 511, t0 = row0 >> 9;
            const int b1 = row1 & 511, t1 = row1 >> 9;
            float* p0 = out + (size_t)b0 * (TS * INP) + t0 * INP + 2 * q;
            float* p1 = out + (size_t)b1 * (TS * INP) + t1 * INP + 2 * q;
#pragma unroll
            for (int nt = 0; nt < 4; nt++) {
                *(float2*)(p0 + nt * 8) = make_float2(acc[nt][0], acc[nt][1]);
                *(float2*)(p1 + nt * 8) = make_float2(acc[nt][2], acc[nt][3]);
            }
        }
        __syncthreads();
    }
}

// ======================= launch =======================
extern "C" void kernel_launch(void* const* d_in, const int* in_sizes, int n_in,
                              void* d_out, int out_size) {
    const float* x     = (const float*)d_in[0];
    const float* eWih  = (const float*)d_in[1];
    const float* eWhh  = (const float*)d_in[2];
    const float* ebih  = (const float*)d_in[3];
    const float* ebhh  = (const float*)d_in[4];
    const float* dWih  = (const float*)d_in[5];
    const float* dWhh  = (const float*)d_in[6];
    const float* dbih  = (const float*)d_in[7];
    const float* dbhh  = (const float*)d_in[8];
    const float* fcW   = (const float*)d_in[9];
    const float* fcb   = (const float*)d_in[10];
    float* out = (float*)d_out;

    prep_all<<<((size_t)TS * NBAT * INP / 4 + 255) / 256, 256>>>(x, eWih, eWhh, ebih, ebhh,
                                                                 dWih, dWhh, dbih, dbhh, fcW);
    encdec_kernel<<<NBAT / NB, 256>>>();
    fc_kernel<<<1024, 256>>>(fcb, out);
}